// round 1
// baseline (speedup 1.0000x reference)
#include <cuda_runtime.h>
#include <math.h>

// Problem constants
#define BB   4
#define LQd  256
#define NSd  24
#define NTd  128
#define Dd   512
#define Hd   8
#define DKd  64

// ---------------- scratch (single device global, no allocs) ----------------
// layout (floats):
//  qs   [1024*512]      @ 0
//  qw   [1024*512]      @ 524288
//  ks   [96*512]        @ 1048576
//  vs   [96*512]        @ 1097728
//  kw   [12288*512]     @ 1146880
//  vw   [12288*512]     @ 7438336
//  attn [4*8*256*24]    @ 13729792
//  ctxs [1024*512]      @ 13926400
//  ctxw [1024*512]      @ 14450688
//  cat  [1024*1024]     @ 14974976
// total 16023552 floats = 64.1 MB
__device__ float g_scratch[16023552];

#define OFF_QS   0
#define OFF_QW   524288
#define OFF_KS   1048576
#define OFF_VS   1097728
#define OFF_KW   1146880
#define OFF_VW   7438336
#define OFF_ATT  13729792
#define OFF_CTXS 13926400
#define OFF_CTXW 14450688
#define OFF_CAT  14974976

// ---------------- generic fp32 SGEMM: C = A(MxK) * B(KxN) + bias ----------------
#define BM 128
#define BN 128
#define BKC 8
#define TM 8
#define TN 8

__global__ __launch_bounds__(256) void sgemm_bias(
    const float* __restrict__ A, const float* __restrict__ B,
    const float* __restrict__ bias, float* __restrict__ C,
    int M, int N, int K, int lda, int ldb, int ldc)
{
    __shared__ float As[BKC][BM];
    __shared__ float Bs[BKC][BN];

    const int tid = threadIdx.x;
    const int tx = tid & 15;       // 0..15 -> N
    const int ty = tid >> 4;       // 0..15 -> M
    const int row0 = blockIdx.y * BM;
    const int col0 = blockIdx.x * BN;

    const int a_row  = tid >> 1;         // 0..127
    const int a_col4 = (tid & 1) * 4;    // 0 or 4
    const int b_row  = tid >> 5;         // 0..7
    const int b_col4 = (tid & 31) * 4;   // 0..124

    float acc[TM][TN];
    #pragma unroll
    for (int i = 0; i < TM; i++)
        #pragma unroll
        for (int j = 0; j < TN; j++) acc[i][j] = 0.f;

    for (int k0 = 0; k0 < K; k0 += BKC) {
        float4 av = make_float4(0.f, 0.f, 0.f, 0.f);
        if (row0 + a_row < M)
            av = *(const float4*)&A[(size_t)(row0 + a_row) * lda + k0 + a_col4];
        As[a_col4 + 0][a_row] = av.x;
        As[a_col4 + 1][a_row] = av.y;
        As[a_col4 + 2][a_row] = av.z;
        As[a_col4 + 3][a_row] = av.w;

        float4 bv = *(const float4*)&B[(size_t)(k0 + b_row) * ldb + col0 + b_col4];
        *(float4*)&Bs[b_row][b_col4] = bv;
        __syncthreads();

        #pragma unroll
        for (int k = 0; k < BKC; k++) {
            float4 ra0 = *(const float4*)&As[k][ty * TM];
            float4 ra1 = *(const float4*)&As[k][ty * TM + 4];
            float4 rb0 = *(const float4*)&Bs[k][tx * TN];
            float4 rb1 = *(const float4*)&Bs[k][tx * TN + 4];
            float ra[TM] = {ra0.x, ra0.y, ra0.z, ra0.w, ra1.x, ra1.y, ra1.z, ra1.w};
            float rb[TN] = {rb0.x, rb0.y, rb0.z, rb0.w, rb1.x, rb1.y, rb1.z, rb1.w};
            #pragma unroll
            for (int i = 0; i < TM; i++)
                #pragma unroll
                for (int j = 0; j < TN; j++)
                    acc[i][j] += ra[i] * rb[j];
        }
        __syncthreads();
    }

    #pragma unroll
    for (int i = 0; i < TM; i++) {
        int r = row0 + ty * TM + i;
        if (r < M) {
            #pragma unroll
            for (int j = 0; j < TN; j++) {
                int c = col0 + tx * TN + j;
                C[(size_t)r * ldc + c] = acc[i][j] + bias[c];
            }
        }
    }
}

// ---------------- sentence-level graph attention ----------------
// grid: (H, B), block: 256 threads (1 thread per query row)
__global__ __launch_bounds__(256) void sent_attn(
    const float* __restrict__ qs,     // [B*LQ, 512]
    const float* __restrict__ ksn,    // [B*NS, 512]
    const float* __restrict__ vsn,    // [B*NS, 512]
    const float* __restrict__ bias_s, // [B,H,LQ,NS]
    const float* __restrict__ gab,    // [B,H,NS,NS]
    float* __restrict__ attns_out,    // [B,H,LQ,NS]
    float* __restrict__ ctxs_out)     // [B*LQ, 512]
{
    const int h = blockIdx.x, b = blockIdx.y;
    const int q = threadIdx.x;

    __shared__ float Ks[NSd][DKd + 1];
    __shared__ float Vs[NSd][DKd + 1];
    __shared__ float G[NSd][NSd + 1];

    for (int idx = q; idx < NSd * DKd; idx += 256) {
        int s = idx >> 6, k = idx & 63;
        Ks[s][k] = ksn[(size_t)(b * NSd + s) * Dd + h * DKd + k];
        Vs[s][k] = vsn[(size_t)(b * NSd + s) * Dd + h * DKd + k];
    }
    for (int idx = q; idx < NSd * NSd; idx += 256) {
        int s = idx / NSd, t = idx % NSd;
        G[s][t] = gab[((size_t)(b * Hd + h) * NSd + s) * NSd + t];
    }
    __syncthreads();

    float qreg[DKd];
    const float* qrow = qs + (size_t)(b * LQd + q) * Dd + h * DKd;
    #pragma unroll
    for (int k = 0; k < DKd; k++) qreg[k] = qrow[k] * 0.125f;

    float a[NSd];
    const float* bsrow = bias_s + ((size_t)(b * Hd + h) * LQd + q) * NSd;
    #pragma unroll
    for (int s = 0; s < NSd; s++) {
        float d = 0.f;
        #pragma unroll
        for (int k = 0; k < DKd; k++) d += qreg[k] * Ks[s][k];
        a[s] = d + bsrow[s];
    }

    // softmax #1
    float m = -1e30f;
    #pragma unroll
    for (int s = 0; s < NSd; s++) m = fmaxf(m, a[s]);
    float smx[NSd];
    float sum = 0.f;
    #pragma unroll
    for (int s = 0; s < NSd; s++) { smx[s] = __expf(a[s] - m); sum += smx[s]; }
    float inv = 1.f / sum;

    // graph prior
    float g[NSd];
    #pragma unroll
    for (int t = 0; t < NSd; t++) {
        float d = 0.f;
        #pragma unroll
        for (int s = 0; s < NSd; s++) d += smx[s] * G[s][t];
        g[t] = d * inv;
    }
    #pragma unroll
    for (int s = 0; s < NSd; s++) a[s] -= 0.5f * g[s] * g[s];   // /(0.5*POS_WIN)^2 == /1.0

    // softmax #2
    m = -1e30f;
    #pragma unroll
    for (int s = 0; s < NSd; s++) m = fmaxf(m, a[s]);
    sum = 0.f;
    #pragma unroll
    for (int s = 0; s < NSd; s++) { a[s] = __expf(a[s] - m); sum += a[s]; }
    inv = 1.f / sum;

    float* arow = attns_out + ((size_t)(b * Hd + h) * LQd + q) * NSd;
    #pragma unroll
    for (int s = 0; s < NSd; s++) { a[s] *= inv; arow[s] = a[s]; }

    // ctx_s = attns @ V
    float* crow = ctxs_out + (size_t)(b * LQd + q) * Dd + h * DKd;
    #pragma unroll
    for (int d = 0; d < DKd; d++) {
        float acc = 0.f;
        #pragma unroll
        for (int s = 0; s < NSd; s++) acc += a[s] * Vs[s][d];
        crow[d] = acc;
    }
}

// ---------------- word-level attention ----------------
// grid: (LQ/32, H, B), block: 256 threads, dynamic smem
#define WPADK 65
#define WPADP 129
#define WSMEM_FLOATS (32 * WPADK + 128 * WPADK + 128 * WPADK + 32 * WPADP)

__global__ __launch_bounds__(256) void word_attn(
    const float* __restrict__ qw,     // [B*LQ, 512]
    const float* __restrict__ kw,     // [B*NS*NT, 512]
    const float* __restrict__ vw,     // [B*NS*NT, 512]
    const float* __restrict__ bias_w, // [B,NS,H,LQ,NT]
    const float* __restrict__ attns,  // [B,H,LQ,NS]
    float* __restrict__ ctxw)         // [B*LQ, 512]
{
    extern __shared__ float sm[];
    float* Qs = sm;                          // [32][65]
    float* Ks = Qs + 32 * WPADK;             // [128][65]
    float* Vs = Ks + 128 * WPADK;            // [128][65]
    float* Ps = Vs + 128 * WPADK;            // [32][129]

    const int tid = threadIdx.x;
    const int tx = tid & 31;
    const int ty = tid >> 5;     // 0..7 == warp id
    const int q0 = blockIdx.x * 32;
    const int h  = blockIdx.y;
    const int b  = blockIdx.z;

    // load Q tile (scaled)
    for (int idx = tid; idx < 32 * 16; idx += 256) {
        int qq = idx >> 4, c = idx & 15;
        float4 v = *(const float4*)(qw + (size_t)(b * LQd + q0 + qq) * Dd + h * DKd + c * 4);
        Qs[qq * WPADK + c * 4 + 0] = v.x * 0.125f;
        Qs[qq * WPADK + c * 4 + 1] = v.y * 0.125f;
        Qs[qq * WPADK + c * 4 + 2] = v.z * 0.125f;
        Qs[qq * WPADK + c * 4 + 3] = v.w * 0.125f;
    }

    float accO[4][2];
    #pragma unroll
    for (int i = 0; i < 4; i++) { accO[i][0] = 0.f; accO[i][1] = 0.f; }

    for (int s = 0; s < NSd; s++) {
        __syncthreads();  // protect Ks/Vs (prev O-accum done) and Qs on first iter
        const float* kb = kw + (size_t)(b * NSd + s) * NTd * Dd + h * DKd;
        const float* vb = vw + (size_t)(b * NSd + s) * NTd * Dd + h * DKd;
        for (int idx = tid; idx < 128 * 16; idx += 256) {
            int t = idx >> 4, c = idx & 15;
            float4 kv = *(const float4*)(kb + (size_t)t * Dd + c * 4);
            Ks[t * WPADK + c * 4 + 0] = kv.x;
            Ks[t * WPADK + c * 4 + 1] = kv.y;
            Ks[t * WPADK + c * 4 + 2] = kv.z;
            Ks[t * WPADK + c * 4 + 3] = kv.w;
            float4 vv = *(const float4*)(vb + (size_t)t * Dd + c * 4);
            Vs[t * WPADK + c * 4 + 0] = vv.x;
            Vs[t * WPADK + c * 4 + 1] = vv.y;
            Vs[t * WPADK + c * 4 + 2] = vv.z;
            Vs[t * WPADK + c * 4 + 3] = vv.w;
        }
        __syncthreads();

        // P = Q @ K^T  (thread computes P[ty*4+i][tx+32*j])
        float p[4][4];
        #pragma unroll
        for (int i = 0; i < 4; i++)
            #pragma unroll
            for (int j = 0; j < 4; j++) p[i][j] = 0.f;

        #pragma unroll 8
        for (int k = 0; k < DKd; k++) {
            float rq[4], rk[4];
            #pragma unroll
            for (int i = 0; i < 4; i++) rq[i] = Qs[(ty * 4 + i) * WPADK + k];
            #pragma unroll
            for (int j = 0; j < 4; j++) rk[j] = Ks[(tx + 32 * j) * WPADK + k];
            #pragma unroll
            for (int i = 0; i < 4; i++)
                #pragma unroll
                for (int j = 0; j < 4; j++) p[i][j] += rq[i] * rk[j];
        }

        // + bias_w, store to Ps
        const float* bb = bias_w + ((size_t)((b * NSd + s) * Hd + h) * LQd + q0) * NTd;
        #pragma unroll
        for (int i = 0; i < 4; i++)
            #pragma unroll
            for (int j = 0; j < 4; j++)
                Ps[(ty * 4 + i) * WPADP + tx + 32 * j] =
                    p[i][j] + bb[(ty * 4 + i) * NTd + tx + 32 * j];
        __syncthreads();

        // row softmax (warp ty handles rows ty*4..ty*4+3), then scale by attns
        #pragma unroll
        for (int rr = 0; rr < 4; rr++) {
            int r = ty * 4 + rr;
            float x0 = Ps[r * WPADP + tx];
            float x1 = Ps[r * WPADP + tx + 32];
            float x2 = Ps[r * WPADP + tx + 64];
            float x3 = Ps[r * WPADP + tx + 96];
            float mx = fmaxf(fmaxf(x0, x1), fmaxf(x2, x3));
            #pragma unroll
            for (int o = 16; o; o >>= 1) mx = fmaxf(mx, __shfl_xor_sync(0xffffffffu, mx, o));
            x0 = __expf(x0 - mx); x1 = __expf(x1 - mx);
            x2 = __expf(x2 - mx); x3 = __expf(x3 - mx);
            float su = x0 + x1 + x2 + x3;
            #pragma unroll
            for (int o = 16; o; o >>= 1) su += __shfl_xor_sync(0xffffffffu, su, o);
            float wsc = attns[((size_t)(b * Hd + h) * LQd + q0 + r) * NSd + s] / su;
            Ps[r * WPADP + tx]      = x0 * wsc;
            Ps[r * WPADP + tx + 32] = x1 * wsc;
            Ps[r * WPADP + tx + 64] = x2 * wsc;
            Ps[r * WPADP + tx + 96] = x3 * wsc;
        }
        __syncthreads();

        // O += P @ V  (thread computes O[ty*4+i][tx+32*j], j=0..1)
        #pragma unroll 4
        for (int t = 0; t < NTd; t++) {
            float rv0 = Vs[t * WPADK + tx];
            float rv1 = Vs[t * WPADK + tx + 32];
            #pragma unroll
            for (int i = 0; i < 4; i++) {
                float rp = Ps[(ty * 4 + i) * WPADP + t];
                accO[i][0] += rp * rv0;
                accO[i][1] += rp * rv1;
            }
        }
    }

    #pragma unroll
    for (int i = 0; i < 4; i++) {
        float* crow = ctxw + (size_t)(b * LQd + q0 + ty * 4 + i) * Dd + h * DKd;
        crow[tx]      = accO[i][0];
        crow[tx + 32] = accO[i][1];
    }
}

// ---------------- host ----------------
extern "C" void kernel_launch(void* const* d_in, const int* in_sizes, int n_in,
                              void* d_out, int out_size)
{
    const float* q      = (const float*)d_in[0];
    const float* k_s    = (const float*)d_in[1];
    const float* v_s    = (const float*)d_in[2];
    const float* k_w    = (const float*)d_in[3];
    const float* v_w    = (const float*)d_in[4];
    const float* bias_w = (const float*)d_in[5];
    const float* bias_s = (const float*)d_in[6];
    const float* gab    = (const float*)d_in[7];

    const float *wq_s, *bq_s, *wk_s, *bk_s, *wv_s, *bv_s;
    const float *wq_w, *bq_w, *wk_w, *bk_w, *wv_w, *bv_w;
    const float *fcs_w, *fcs_b, *fcw_w, *fcw_b, *fco_w, *fco_b;

    if (in_sizes[9] == 512) {
        // reference-signature order (weight/bias interleaved)
        wq_s = (const float*)d_in[8];  bq_s = (const float*)d_in[9];
        wk_s = (const float*)d_in[10]; bk_s = (const float*)d_in[11];
        wv_s = (const float*)d_in[12]; bv_s = (const float*)d_in[13];
        wq_w = (const float*)d_in[14]; bq_w = (const float*)d_in[15];
        wk_w = (const float*)d_in[16]; bk_w = (const float*)d_in[17];
        wv_w = (const float*)d_in[18]; bv_w = (const float*)d_in[19];
        fcs_w = (const float*)d_in[20]; fcs_b = (const float*)d_in[21];
        fcw_w = (const float*)d_in[22]; fcw_b = (const float*)d_in[23];
        fco_w = (const float*)d_in[24]; fco_b = (const float*)d_in[25];
    } else {
        // setup_inputs dict order (weights grouped, then biases)
        wq_s = (const float*)d_in[8];  wk_s = (const float*)d_in[9];
        wv_s = (const float*)d_in[10]; wq_w = (const float*)d_in[11];
        wk_w = (const float*)d_in[12]; wv_w = (const float*)d_in[13];
        fcs_w = (const float*)d_in[14]; fcw_w = (const float*)d_in[15];
        bq_s = (const float*)d_in[16]; bk_s = (const float*)d_in[17];
        bv_s = (const float*)d_in[18]; bq_w = (const float*)d_in[19];
        bk_w = (const float*)d_in[20]; bv_w = (const float*)d_in[21];
        fcs_b = (const float*)d_in[22]; fcw_b = (const float*)d_in[23];
        fco_w = (const float*)d_in[24]; fco_b = (const float*)d_in[25];
    }

    float* scratch = nullptr;
    cudaGetSymbolAddress((void**)&scratch, g_scratch);
    float* s_qs   = scratch + OFF_QS;
    float* s_qw   = scratch + OFF_QW;
    float* s_ks   = scratch + OFF_KS;
    float* s_vs   = scratch + OFF_VS;
    float* s_kw   = scratch + OFF_KW;
    float* s_vw   = scratch + OFF_VW;
    float* s_att  = scratch + OFF_ATT;
    float* s_ctxs = scratch + OFF_CTXS;
    float* s_ctxw = scratch + OFF_CTXW;
    float* s_cat  = scratch + OFF_CAT;

    dim3 blk(256);

    // projections
    sgemm_bias<<<dim3(4, 8), blk>>>(q,   wq_s, bq_s, s_qs, 1024, 512, 512, 512, 512, 512);
    sgemm_bias<<<dim3(4, 8), blk>>>(q,   wq_w, bq_w, s_qw, 1024, 512, 512, 512, 512, 512);
    sgemm_bias<<<dim3(4, 1), blk>>>(k_s, wk_s, bk_s, s_ks,   96, 512, 512, 512, 512, 512);
    sgemm_bias<<<dim3(4, 1), blk>>>(v_s, wv_s, bv_s, s_vs,   96, 512, 512, 512, 512, 512);
    sgemm_bias<<<dim3(4, 96), blk>>>(k_w, wk_w, bk_w, s_kw, 12288, 512, 512, 512, 512, 512);
    sgemm_bias<<<dim3(4, 96), blk>>>(v_w, wv_w, bv_w, s_vw, 12288, 512, 512, 512, 512, 512);

    // sentence-level graph attention -> attns, ctx_s
    sent_attn<<<dim3(Hd, BB), blk>>>(s_qs, s_ks, s_vs, bias_s, gab, s_att, s_ctxs);

    // word-level attention -> ctx_w
    size_t wsmem = WSMEM_FLOATS * sizeof(float);
    cudaFuncSetAttribute(word_attn, cudaFuncAttributeMaxDynamicSharedMemorySize, (int)wsmem);
    word_attn<<<dim3(LQd / 32, Hd, BB), blk, wsmem>>>(s_qw, s_kw, s_vw, bias_w, s_att, s_ctxw);

    // final FCs: cat = [ctx_s @ fcs_w + b | ctx_w @ fcw_w + b], out = cat @ fco_w + b
    sgemm_bias<<<dim3(4, 8), blk>>>(s_ctxs, fcs_w, fcs_b, s_cat,       1024, 512, 512, 512, 512, 1024);
    sgemm_bias<<<dim3(4, 8), blk>>>(s_ctxw, fcw_w, fcw_b, s_cat + 512, 1024, 512, 512, 512, 512, 1024);
    sgemm_bias<<<dim3(4, 8), blk>>>(s_cat,  fco_w, fco_b, (float*)d_out, 1024, 512, 1024, 1024, 512, 512);
}

// round 3
// speedup vs baseline: 1.8034x; 1.8034x over previous
#include <cuda_runtime.h>
#include <math.h>
#include <stdint.h>

// Problem constants
#define BB   4
#define LQd  256
#define NSd  24
#define NTd  128
#define Dd   512
#define Hd   8
#define DKd  64

// ---------------- scratch ----------------
__device__ float g_scratch[16023552];
#define OFF_QS   0
#define OFF_QW   524288
#define OFF_KS   1048576
#define OFF_VS   1097728
#define OFF_KW   1146880
#define OFF_VW   7438336
#define OFF_ATT  13729792
#define OFF_CTXS 13926400
#define OFF_CTXW 14450688
#define OFF_CAT  14974976

// ---------------- tf32 helpers ----------------
__device__ __forceinline__ uint32_t f2tf32(float x) {
    uint32_t r;
    asm("cvt.rna.tf32.f32 %0, %1;" : "=r"(r) : "f"(x));
    return r;
}
__device__ __forceinline__ void split_tf32(float x, uint32_t& hi, uint32_t& lo) {
    hi = f2tf32(x);
    lo = f2tf32(x - __uint_as_float(hi));
}
__device__ __forceinline__ void mma_tf32(float d[4],
                                         uint32_t a0, uint32_t a1, uint32_t a2, uint32_t a3,
                                         uint32_t b0, uint32_t b1) {
    asm volatile(
        "mma.sync.aligned.m16n8k8.row.col.f32.tf32.tf32.f32 "
        "{%0,%1,%2,%3},{%4,%5,%6,%7},{%8,%9},{%0,%1,%2,%3};"
        : "+f"(d[0]), "+f"(d[1]), "+f"(d[2]), "+f"(d[3])
        : "r"(a0), "r"(a1), "r"(a2), "r"(a3), "r"(b0), "r"(b1));
}

__device__ __forceinline__ void cp_async16(uint32_t smem_addr, const void* gptr, int src_bytes) {
    asm volatile("cp.async.cg.shared.global [%0], [%1], 16, %2;"
                 :: "r"(smem_addr), "l"(gptr), "r"(src_bytes) : "memory");
}
__device__ __forceinline__ void cp_commit() { asm volatile("cp.async.commit_group;" ::: "memory"); }
template <int N>
__device__ __forceinline__ void cp_wait() { asm volatile("cp.async.wait_group %0;" :: "n"(N) : "memory"); }

// ---------------- tensor-core GEMM: C = A(MxK) @ B(KxN) + bias ----------------
// 128x128 block tile, BK=32, 256 threads (8 warps: 2x4, warp tile 64x32)
#define GAPAD 36   // A smem row stride (floats), 32 cols
#define GBPAD 132  // B smem row stride (floats), 128 cols
#define GSTAGE (128 * GAPAD + 32 * GBPAD)   // 8832 floats per stage
#define GSMEM_BYTES (2 * GSTAGE * 4)        // 70656

__global__ __launch_bounds__(256) void gemm_tc(
    const float* __restrict__ A, const float* __restrict__ B,
    const float* __restrict__ bias, float* __restrict__ C,
    int M, int N, int K, int lda, int ldb, int ldc)
{
    extern __shared__ float gsm[];

    const int tid = threadIdx.x;
    const int wid = tid >> 5;
    const int lane = tid & 31;
    const int g = lane >> 2;
    const int t = lane & 3;
    const int wm = wid & 1;
    const int wn = wid >> 1;
    const int row0 = blockIdx.y * 128;
    const int col0 = blockIdx.x * 128;

    float d[4][4][4];
    #pragma unroll
    for (int mt = 0; mt < 4; mt++)
        #pragma unroll
        for (int nt = 0; nt < 4; nt++)
            #pragma unroll
            for (int j = 0; j < 4; j++) d[mt][nt][j] = 0.f;

    const int ktiles = K >> 5;

    {
        float* As = gsm;
        float* Bs = gsm + 128 * GAPAD;
        #pragma unroll
        for (int i = 0; i < 4; i++) {
            int id = tid + 256 * i;
            int ar = id >> 3, ac = id & 7;
            int r = row0 + ar;
            int rc = r < M ? r : (M - 1);
            cp_async16((uint32_t)__cvta_generic_to_shared(&As[ar * GAPAD + ac * 4]),
                       &A[(size_t)rc * lda + ac * 4], r < M ? 16 : 0);
            int br = id >> 5, bc = id & 31;
            cp_async16((uint32_t)__cvta_generic_to_shared(&Bs[br * GBPAD + bc * 4]),
                       &B[(size_t)br * ldb + col0 + bc * 4], 16);
        }
        cp_commit();
    }

    for (int kt = 0; kt < ktiles; kt++) {
        if (kt + 1 < ktiles) {
            float* As = gsm + ((kt + 1) & 1) * GSTAGE;
            float* Bs = As + 128 * GAPAD;
            int k0 = (kt + 1) << 5;
            #pragma unroll
            for (int i = 0; i < 4; i++) {
                int id = tid + 256 * i;
                int ar = id >> 3, ac = id & 7;
                int r = row0 + ar;
                int rc = r < M ? r : (M - 1);
                cp_async16((uint32_t)__cvta_generic_to_shared(&As[ar * GAPAD + ac * 4]),
                           &A[(size_t)rc * lda + k0 + ac * 4], r < M ? 16 : 0);
                int br = id >> 5, bc = id & 31;
                cp_async16((uint32_t)__cvta_generic_to_shared(&Bs[br * GBPAD + bc * 4]),
                           &B[(size_t)(k0 + br) * ldb + col0 + bc * 4], 16);
            }
            cp_commit();
            cp_wait<1>();
        } else {
            cp_wait<0>();
        }
        __syncthreads();

        const float* As = gsm + (kt & 1) * GSTAGE;
        const float* Bs = As + 128 * GAPAD;

        #pragma unroll
        for (int ks = 0; ks < 4; ks++) {
            const int k = ks * 8;
            uint32_t ah[4][4], al[4][4];
            #pragma unroll
            for (int mt = 0; mt < 4; mt++) {
                int r0 = wm * 64 + mt * 16 + g;
                float x0 = As[r0 * GAPAD + k + t];
                float x1 = As[(r0 + 8) * GAPAD + k + t];
                float x2 = As[r0 * GAPAD + k + t + 4];
                float x3 = As[(r0 + 8) * GAPAD + k + t + 4];
                split_tf32(x0, ah[mt][0], al[mt][0]);
                split_tf32(x1, ah[mt][1], al[mt][1]);
                split_tf32(x2, ah[mt][2], al[mt][2]);
                split_tf32(x3, ah[mt][3], al[mt][3]);
            }
            #pragma unroll
            for (int nt = 0; nt < 4; nt++) {
                int c = wn * 32 + nt * 8 + g;
                float y0 = Bs[(k + t) * GBPAD + c];
                float y1 = Bs[(k + t + 4) * GBPAD + c];
                uint32_t bh0, bl0, bh1, bl1;
                split_tf32(y0, bh0, bl0);
                split_tf32(y1, bh1, bl1);
                #pragma unroll
                for (int mt = 0; mt < 4; mt++) {
                    mma_tf32(d[mt][nt], ah[mt][0], ah[mt][1], ah[mt][2], ah[mt][3], bh0, bh1);
                    mma_tf32(d[mt][nt], ah[mt][0], ah[mt][1], ah[mt][2], ah[mt][3], bl0, bl1);
                    mma_tf32(d[mt][nt], al[mt][0], al[mt][1], al[mt][2], al[mt][3], bh0, bh1);
                }
            }
        }
        __syncthreads();
    }

    #pragma unroll
    for (int mt = 0; mt < 4; mt++) {
        #pragma unroll
        for (int nt = 0; nt < 4; nt++) {
            int r = row0 + wm * 64 + mt * 16 + g;
            int c = col0 + wn * 32 + nt * 8 + 2 * t;
            float2 bz = *(const float2*)&bias[c];
            if (r < M) {
                float2 o = make_float2(d[mt][nt][0] + bz.x, d[mt][nt][1] + bz.y);
                *(float2*)&C[(size_t)r * ldc + c] = o;
            }
            if (r + 8 < M) {
                float2 o = make_float2(d[mt][nt][2] + bz.x, d[mt][nt][3] + bz.y);
                *(float2*)&C[(size_t)(r + 8) * ldc + c] = o;
            }
        }
    }
}

// ---------------- sentence-level graph attention ----------------
__global__ __launch_bounds__(256) void sent_attn(
    const float* __restrict__ qs, const float* __restrict__ ksn,
    const float* __restrict__ vsn, const float* __restrict__ bias_s,
    const float* __restrict__ gab,
    float* __restrict__ attns_out, float* __restrict__ ctxs_out)
{
    const int h = blockIdx.x, b = blockIdx.y;
    const int q = threadIdx.x;

    __shared__ float Ks[NSd][DKd + 1];
    __shared__ float Vs[NSd][DKd + 1];
    __shared__ float G[NSd][NSd + 1];

    for (int idx = q; idx < NSd * DKd; idx += 256) {
        int s = idx >> 6, k = idx & 63;
        Ks[s][k] = ksn[(size_t)(b * NSd + s) * Dd + h * DKd + k];
        Vs[s][k] = vsn[(size_t)(b * NSd + s) * Dd + h * DKd + k];
    }
    for (int idx = q; idx < NSd * NSd; idx += 256) {
        int s = idx / NSd, tt = idx % NSd;
        G[s][tt] = gab[((size_t)(b * Hd + h) * NSd + s) * NSd + tt];
    }
    __syncthreads();

    float qreg[DKd];
    const float* qrow = qs + (size_t)(b * LQd + q) * Dd + h * DKd;
    #pragma unroll
    for (int k = 0; k < DKd; k++) qreg[k] = qrow[k] * 0.125f;

    float a[NSd];
    const float* bsrow = bias_s + ((size_t)(b * Hd + h) * LQd + q) * NSd;
    #pragma unroll
    for (int s = 0; s < NSd; s++) {
        float dd = 0.f;
        #pragma unroll
        for (int k = 0; k < DKd; k++) dd += qreg[k] * Ks[s][k];
        a[s] = dd + bsrow[s];
    }

    float m = -1e30f;
    #pragma unroll
    for (int s = 0; s < NSd; s++) m = fmaxf(m, a[s]);
    float smx[NSd]; float sum = 0.f;
    #pragma unroll
    for (int s = 0; s < NSd; s++) { smx[s] = __expf(a[s] - m); sum += smx[s]; }
    float inv = 1.f / sum;

    float gg[NSd];
    #pragma unroll
    for (int tt = 0; tt < NSd; tt++) {
        float dd = 0.f;
        #pragma unroll
        for (int s = 0; s < NSd; s++) dd += smx[s] * G[s][tt];
        gg[tt] = dd * inv;
    }
    #pragma unroll
    for (int s = 0; s < NSd; s++) a[s] -= 0.5f * gg[s] * gg[s];

    m = -1e30f;
    #pragma unroll
    for (int s = 0; s < NSd; s++) m = fmaxf(m, a[s]);
    sum = 0.f;
    #pragma unroll
    for (int s = 0; s < NSd; s++) { a[s] = __expf(a[s] - m); sum += a[s]; }
    inv = 1.f / sum;

    float* arow = attns_out + ((size_t)(b * Hd + h) * LQd + q) * NSd;
    #pragma unroll
    for (int s = 0; s < NSd; s++) { a[s] *= inv; arow[s] = a[s]; }

    float* crow = ctxs_out + (size_t)(b * LQd + q) * Dd + h * DKd;
    #pragma unroll
    for (int dd = 0; dd < DKd; dd++) {
        float acc = 0.f;
        #pragma unroll
        for (int s = 0; s < NSd; s++) acc += a[s] * Vs[s][dd];
        crow[dd] = acc;
    }
}

// ---------------- word-level attention (tensor-core, 3xTF32) ----------------
// grid (LQ/32, H, B), 256 threads (8 warps).
// smem: Qh/Ql tf32 [32][68], Ks/Vs fp32 [128][68], Ps fp32 [32][132]
#define WQPAD 68   // Q row stride: 64 cols + 4 pad (was 36: OVERLAP BUG)
#define WKPAD 68
#define WPPAD 132
#define WSM_QH 0
#define WSM_QL (32 * WQPAD)
#define WSM_K  (2 * 32 * WQPAD)
#define WSM_V  (WSM_K + 128 * WKPAD)
#define WSM_P  (WSM_V + 128 * WKPAD)
#define WSMEM_WORDS (WSM_P + 32 * WPPAD)   // 25984 floats = 103936 B

__global__ __launch_bounds__(256) void word_attn_tc(
    const float* __restrict__ qw, const float* __restrict__ kw,
    const float* __restrict__ vw, const float* __restrict__ bias_w,
    const float* __restrict__ attns, float* __restrict__ ctxw)
{
    extern __shared__ float wsm[];
    uint32_t* Qh = (uint32_t*)(wsm + WSM_QH);
    uint32_t* Ql = (uint32_t*)(wsm + WSM_QL);
    float* Ks = wsm + WSM_K;
    float* Vs = wsm + WSM_V;
    float* Ps = wsm + WSM_P;

    const int tid = threadIdx.x;
    const int wid = tid >> 5;
    const int lane = tid & 31;
    const int g = lane >> 2;
    const int t = lane & 3;
    const int wm = wid & 1;
    const int wn = wid >> 1;
    const int q0 = blockIdx.x * 32;
    const int h  = blockIdx.y;
    const int b  = blockIdx.z;

    // load Q (scaled), split to tf32 hi/lo
    #pragma unroll
    for (int i = 0; i < 2; i++) {
        int id = tid + 256 * i;
        int qr = id >> 4, qc = id & 15;
        float4 v = *(const float4*)(qw + (size_t)(b * LQd + q0 + qr) * Dd + h * DKd + qc * 4);
        float vv[4] = {v.x * 0.125f, v.y * 0.125f, v.z * 0.125f, v.w * 0.125f};
        #pragma unroll
        for (int j = 0; j < 4; j++) {
            uint32_t hi, lo;
            split_tf32(vv[j], hi, lo);
            Qh[qr * WQPAD + qc * 4 + j] = hi;
            Ql[qr * WQPAD + qc * 4 + j] = lo;
        }
    }

    float oacc[2][4];
    #pragma unroll
    for (int nt = 0; nt < 2; nt++)
        #pragma unroll
        for (int j = 0; j < 4; j++) oacc[nt][j] = 0.f;

    for (int s = 0; s < NSd; s++) {
        __syncthreads();
        const float* kb = kw + (size_t)(b * NSd + s) * NTd * Dd + h * DKd;
        const float* vb = vw + (size_t)(b * NSd + s) * NTd * Dd + h * DKd;
        #pragma unroll
        for (int i = 0; i < 8; i++) {
            int id = tid + 256 * i;
            int kr = id >> 4, kc = id & 15;
            float4 kv = *(const float4*)(kb + (size_t)kr * Dd + kc * 4);
            *(float4*)&Ks[kr * WKPAD + kc * 4] = kv;
            float4 vv = *(const float4*)(vb + (size_t)kr * Dd + kc * 4);
            *(float4*)&Vs[kr * WKPAD + kc * 4] = vv;
        }
        __syncthreads();

        // ---- P = Q @ K^T (warp tile 16x32) ----
        float pacc[4][4];
        #pragma unroll
        for (int nt = 0; nt < 4; nt++)
            #pragma unroll
            for (int j = 0; j < 4; j++) pacc[nt][j] = 0.f;

        #pragma unroll
        for (int ks = 0; ks < 8; ks++) {
            const int k = ks * 8;
            int r0 = wm * 16 + g;
            uint32_t ah0 = Qh[r0 * WQPAD + k + t];
            uint32_t ah1 = Qh[(r0 + 8) * WQPAD + k + t];
            uint32_t ah2 = Qh[r0 * WQPAD + k + t + 4];
            uint32_t ah3 = Qh[(r0 + 8) * WQPAD + k + t + 4];
            uint32_t al0 = Ql[r0 * WQPAD + k + t];
            uint32_t al1 = Ql[(r0 + 8) * WQPAD + k + t];
            uint32_t al2 = Ql[r0 * WQPAD + k + t + 4];
            uint32_t al3 = Ql[(r0 + 8) * WQPAD + k + t + 4];
            #pragma unroll
            for (int nt = 0; nt < 4; nt++) {
                int c = wn * 32 + nt * 8 + g;
                float y0 = Ks[c * WKPAD + k + t];
                float y1 = Ks[c * WKPAD + k + t + 4];
                uint32_t bh0, bl0, bh1, bl1;
                split_tf32(y0, bh0, bl0);
                split_tf32(y1, bh1, bl1);
                mma_tf32(pacc[nt], ah0, ah1, ah2, ah3, bh0, bh1);
                mma_tf32(pacc[nt], ah0, ah1, ah2, ah3, bl0, bl1);
                mma_tf32(pacc[nt], al0, al1, al2, al3, bh0, bh1);
            }
        }
        #pragma unroll
        for (int nt = 0; nt < 4; nt++) {
            int r = wm * 16 + g;
            int c = wn * 32 + nt * 8 + 2 * t;
            *(float2*)&Ps[r * WPPAD + c] = make_float2(pacc[nt][0], pacc[nt][1]);
            *(float2*)&Ps[(r + 8) * WPPAD + c] = make_float2(pacc[nt][2], pacc[nt][3]);
        }
        __syncthreads();

        // ---- softmax + bias + attns scaling ----
        const float* bb = bias_w + ((size_t)((b * NSd + s) * Hd + h) * LQd + q0) * NTd;
        #pragma unroll
        for (int rr = 0; rr < 4; rr++) {
            int r = wid * 4 + rr;
            float x0 = Ps[r * WPPAD + lane]       + bb[r * NTd + lane];
            float x1 = Ps[r * WPPAD + lane + 32]  + bb[r * NTd + lane + 32];
            float x2 = Ps[r * WPPAD + lane + 64]  + bb[r * NTd + lane + 64];
            float x3 = Ps[r * WPPAD + lane + 96]  + bb[r * NTd + lane + 96];
            float mx = fmaxf(fmaxf(x0, x1), fmaxf(x2, x3));
            #pragma unroll
            for (int o = 16; o; o >>= 1) mx = fmaxf(mx, __shfl_xor_sync(0xffffffffu, mx, o));
            x0 = __expf(x0 - mx); x1 = __expf(x1 - mx);
            x2 = __expf(x2 - mx); x3 = __expf(x3 - mx);
            float su = x0 + x1 + x2 + x3;
            #pragma unroll
            for (int o = 16; o; o >>= 1) su += __shfl_xor_sync(0xffffffffu, su, o);
            float wsc = attns[((size_t)(b * Hd + h) * LQd + q0 + r) * NSd + s] / su;
            Ps[r * WPPAD + lane]      = x0 * wsc;
            Ps[r * WPPAD + lane + 32] = x1 * wsc;
            Ps[r * WPPAD + lane + 64] = x2 * wsc;
            Ps[r * WPPAD + lane + 96] = x3 * wsc;
        }
        __syncthreads();

        // ---- O += P @ V (warp tile 16x16) ----
        #pragma unroll
        for (int ks = 0; ks < 16; ks++) {
            const int k = ks * 8;
            int r0 = wm * 16 + g;
            float p0 = Ps[r0 * WPPAD + k + t];
            float p1 = Ps[(r0 + 8) * WPPAD + k + t];
            float p2 = Ps[r0 * WPPAD + k + t + 4];
            float p3 = Ps[(r0 + 8) * WPPAD + k + t + 4];
            uint32_t ah0, al0, ah1, al1, ah2, al2, ah3, al3;
            split_tf32(p0, ah0, al0);
            split_tf32(p1, ah1, al1);
            split_tf32(p2, ah2, al2);
            split_tf32(p3, ah3, al3);
            #pragma unroll
            for (int nt = 0; nt < 2; nt++) {
                int c = wn * 16 + nt * 8 + g;
                float y0 = Vs[(k + t) * WKPAD + c];
                float y1 = Vs[(k + t + 4) * WKPAD + c];
                uint32_t bh0, bl0, bh1, bl1;
                split_tf32(y0, bh0, bl0);
                split_tf32(y1, bh1, bl1);
                mma_tf32(oacc[nt], ah0, ah1, ah2, ah3, bh0, bh1);
                mma_tf32(oacc[nt], ah0, ah1, ah2, ah3, bl0, bl1);
                mma_tf32(oacc[nt], al0, al1, al2, al3, bh0, bh1);
            }
        }
    }

    #pragma unroll
    for (int nt = 0; nt < 2; nt++) {
        int r = q0 + wm * 16 + g;
        int c = h * DKd + wn * 16 + nt * 8 + 2 * t;
        *(float2*)&ctxw[(size_t)(b * LQd + r) * Dd + c] =
            make_float2(oacc[nt][0], oacc[nt][1]);
        *(float2*)&ctxw[(size_t)(b * LQd + r + 8) * Dd + c] =
            make_float2(oacc[nt][2], oacc[nt][3]);
    }
}

// ---------------- host ----------------
extern "C" void kernel_launch(void* const* d_in, const int* in_sizes, int n_in,
                              void* d_out, int out_size)
{
    const float* q      = (const float*)d_in[0];
    const float* k_s    = (const float*)d_in[1];
    const float* v_s    = (const float*)d_in[2];
    const float* k_w    = (const float*)d_in[3];
    const float* v_w    = (const float*)d_in[4];
    const float* bias_w = (const float*)d_in[5];
    const float* bias_s = (const float*)d_in[6];
    const float* gab    = (const float*)d_in[7];

    const float *wq_s, *bq_s, *wk_s, *bk_s, *wv_s, *bv_s;
    const float *wq_w, *bq_w, *wk_w, *bk_w, *wv_w, *bv_w;
    const float *fcs_w, *fcs_b, *fcw_w, *fcw_b, *fco_w, *fco_b;

    if (in_sizes[9] == 512) {
        wq_s = (const float*)d_in[8];  bq_s = (const float*)d_in[9];
        wk_s = (const float*)d_in[10]; bk_s = (const float*)d_in[11];
        wv_s = (const float*)d_in[12]; bv_s = (const float*)d_in[13];
        wq_w = (const float*)d_in[14]; bq_w = (const float*)d_in[15];
        wk_w = (const float*)d_in[16]; bk_w = (const float*)d_in[17];
        wv_w = (const float*)d_in[18]; bv_w = (const float*)d_in[19];
        fcs_w = (const float*)d_in[20]; fcs_b = (const float*)d_in[21];
        fcw_w = (const float*)d_in[22]; fcw_b = (const float*)d_in[23];
        fco_w = (const float*)d_in[24]; fco_b = (const float*)d_in[25];
    } else {
        wq_s = (const float*)d_in[8];  wk_s = (const float*)d_in[9];
        wv_s = (const float*)d_in[10]; wq_w = (const float*)d_in[11];
        wk_w = (const float*)d_in[12]; wv_w = (const float*)d_in[13];
        fcs_w = (const float*)d_in[14]; fcw_w = (const float*)d_in[15];
        bq_s = (const float*)d_in[16]; bk_s = (const float*)d_in[17];
        bv_s = (const float*)d_in[18]; bq_w = (const float*)d_in[19];
        bk_w = (const float*)d_in[20]; bv_w = (const float*)d_in[21];
        fcs_b = (const float*)d_in[22]; fcw_b = (const float*)d_in[23];
        fco_w = (const float*)d_in[24]; fco_b = (const float*)d_in[25];
    }

    float* scratch = nullptr;
    cudaGetSymbolAddress((void**)&scratch, g_scratch);
    float* s_qs   = scratch + OFF_QS;
    float* s_qw   = scratch + OFF_QW;
    float* s_ks   = scratch + OFF_KS;
    float* s_vs   = scratch + OFF_VS;
    float* s_kw   = scratch + OFF_KW;
    float* s_vw   = scratch + OFF_VW;
    float* s_att  = scratch + OFF_ATT;
    float* s_ctxs = scratch + OFF_CTXS;
    float* s_ctxw = scratch + OFF_CTXW;
    float* s_cat  = scratch + OFF_CAT;

    cudaFuncSetAttribute(gemm_tc, cudaFuncAttributeMaxDynamicSharedMemorySize, GSMEM_BYTES);
    cudaFuncSetAttribute(word_attn_tc, cudaFuncAttributeMaxDynamicSharedMemorySize,
                         WSMEM_WORDS * (int)sizeof(float));

    dim3 blk(256);

    gemm_tc<<<dim3(4, 8),  blk, GSMEM_BYTES>>>(q,   wq_s, bq_s, s_qs, 1024, 512, 512, 512, 512, 512);
    gemm_tc<<<dim3(4, 8),  blk, GSMEM_BYTES>>>(q,   wq_w, bq_w, s_qw, 1024, 512, 512, 512, 512, 512);
    gemm_tc<<<dim3(4, 1),  blk, GSMEM_BYTES>>>(k_s, wk_s, bk_s, s_ks,   96, 512, 512, 512, 512, 512);
    gemm_tc<<<dim3(4, 1),  blk, GSMEM_BYTES>>>(v_s, wv_s, bv_s, s_vs,   96, 512, 512, 512, 512, 512);
    gemm_tc<<<dim3(4, 96), blk, GSMEM_BYTES>>>(k_w, wk_w, bk_w, s_kw, 12288, 512, 512, 512, 512, 512);
    gemm_tc<<<dim3(4, 96), blk, GSMEM_BYTES>>>(v_w, wv_w, bv_w, s_vw, 12288, 512, 512, 512, 512, 512);

    sent_attn<<<dim3(Hd, BB), blk>>>(s_qs, s_ks, s_vs, bias_s, gab, s_att, s_ctxs);

    word_attn_tc<<<dim3(LQd / 32, Hd, BB), blk, WSMEM_WORDS * sizeof(float)>>>(
        s_qw, s_kw, s_vw, bias_w, s_att, s_ctxw);

    gemm_tc<<<dim3(4, 8), blk, GSMEM_BYTES>>>(s_ctxs, fcs_w, fcs_b, s_cat,       1024, 512, 512, 512, 512, 1024);
    gemm_tc<<<dim3(4, 8), blk, GSMEM_BYTES>>>(s_ctxw, fcw_w, fcw_b, s_cat + 512, 1024, 512, 512, 512, 512, 1024);
    gemm_tc<<<dim3(4, 8), blk, GSMEM_BYTES>>>(s_cat,  fco_w, fco_b, (float*)d_out, 1024, 512, 1024, 1024, 512, 512);
}

// round 4
// speedup vs baseline: 2.0423x; 1.1324x over previous
#include <cuda_runtime.h>
#include <math.h>
#include <stdint.h>

// Problem constants
#define BB   4
#define LQd  256
#define NSd  24
#define NTd  128
#define Dd   512
#define Hd   8
#define DKd  64

// ---------------- scratch ----------------
// original 16023552 floats + 9 weight hi/lo splits (2*2621440)
#define OFF_QS   0
#define OFF_QW   524288
#define OFF_KS   1048576
#define OFF_VS   1097728
#define OFF_KW   1146880
#define OFF_VW   7438336
#define OFF_ATT  13729792
#define OFF_CTXS 13926400
#define OFF_CTXW 14450688
#define OFF_CAT  14974976
#define OFF_WH   16023552
#define OFF_WL   (OFF_WH + 2621440)
#define SCRATCH_TOTAL (OFF_WL + 2621440)
__device__ float g_scratch[SCRATCH_TOTAL];

// weight order in split buffers: wq_s wk_s wv_s wq_w wk_w wv_w fcs_w fcw_w fco_w
#define WOFF(i) ((i) * 262144)   // i<8; fco at WOFF(8), size 524288

// ---------------- tf32 helpers ----------------
__device__ __forceinline__ uint32_t f2tf32(float x) {
    uint32_t r;
    asm("cvt.rna.tf32.f32 %0, %1;" : "=r"(r) : "f"(x));
    return r;
}
__device__ __forceinline__ void split_tf32(float x, uint32_t& hi, uint32_t& lo) {
    hi = f2tf32(x);
    lo = f2tf32(x - __uint_as_float(hi));
}
__device__ __forceinline__ void mma_tf32(float d[4],
                                         uint32_t a0, uint32_t a1, uint32_t a2, uint32_t a3,
                                         uint32_t b0, uint32_t b1) {
    asm volatile(
        "mma.sync.aligned.m16n8k8.row.col.f32.tf32.tf32.f32 "
        "{%0,%1,%2,%3},{%4,%5,%6,%7},{%8,%9},{%0,%1,%2,%3};"
        : "+f"(d[0]), "+f"(d[1]), "+f"(d[2]), "+f"(d[3])
        : "r"(a0), "r"(a1), "r"(a2), "r"(a3), "r"(b0), "r"(b1));
}

__device__ __forceinline__ void cp_async16(uint32_t smem_addr, const void* gptr, int src_bytes) {
    asm volatile("cp.async.cg.shared.global [%0], [%1], 16, %2;"
                 :: "r"(smem_addr), "l"(gptr), "r"(src_bytes) : "memory");
}
__device__ __forceinline__ void cp_commit() { asm volatile("cp.async.commit_group;" ::: "memory"); }
template <int N>
__device__ __forceinline__ void cp_wait() { asm volatile("cp.async.wait_group %0;" :: "n"(N) : "memory"); }

// ---------------- weight split prep ----------------
struct PrepArgs { const float* src[9]; };

__global__ __launch_bounds__(256) void prep_split(PrepArgs args, float* wh, float* wl)
{
    int w = blockIdx.y;
    int n = (w < 8) ? 262144 : 524288;
    const float* s = args.src[w];
    float* dh = wh + WOFF(w);
    float* dl = wl + WOFF(w);
    for (int i = blockIdx.x * 256 + threadIdx.x; i < n; i += gridDim.x * 256) {
        float x = s[i];
        uint32_t hi, lo;
        split_tf32(x, hi, lo);
        dh[i] = __uint_as_float(hi);
        dl[i] = __uint_as_float(lo);
    }
}

// ---------------- tensor-core GEMM v2 ----------------
// 128x128 block tile, BK=32, 512 threads (16 warps: 4x4, warp tile 32x32).
// B pre-split (hi/lo) in gmem; A split inline. Double-buffered cp.async.
#define GAPAD 36    // A smem row stride, 32 cols
#define GBPAD 136   // B smem row stride, 128 cols -> (8t+g) conflict-free frag loads
#define G_AS  (128 * GAPAD)          // 4608
#define G_BS  (32 * GBPAD)           // 4352
#define GSTAGE (G_AS + 2 * G_BS)     // 13312 floats
#define GSMEM_BYTES (2 * GSTAGE * 4) // 106496

__global__ __launch_bounds__(512) void gemm_tc2(
    const float* __restrict__ A0, const float* __restrict__ A1,
    const float* __restrict__ Bh0, const float* __restrict__ Bl0,
    const float* __restrict__ Bh1, const float* __restrict__ Bl1,
    const float* __restrict__ bias0, const float* __restrict__ bias1,
    float* __restrict__ C0, float* __restrict__ C1,
    int M, int N, int K, int lda, int ldb, int ldc)
{
    extern __shared__ float gsm[];

    const int z = blockIdx.z;
    const float* A    = z ? A1 : A0;
    const float* Bh_g = z ? Bh1 : Bh0;
    const float* Bl_g = z ? Bl1 : Bl0;
    const float* bias = z ? bias1 : bias0;
    float* C          = z ? C1 : C0;

    const int tid = threadIdx.x;
    const int wid = tid >> 5;
    const int lane = tid & 31;
    const int g = lane >> 2;
    const int t = lane & 3;
    const int wm = wid & 3;       // 4 row groups of 32
    const int wn = wid >> 2;      // 4 col groups of 32
    const int row0 = blockIdx.y * 128;
    const int col0 = blockIdx.x * 128;

    float d[2][4][4];
    #pragma unroll
    for (int mt = 0; mt < 2; mt++)
        #pragma unroll
        for (int nt = 0; nt < 4; nt++)
            #pragma unroll
            for (int j = 0; j < 4; j++) d[mt][nt][j] = 0.f;

    const int ktiles = K >> 5;

    // issue tile 0
    {
        float* As  = gsm;
        float* Bhs = gsm + G_AS;
        float* Bls = Bhs + G_BS;
        #pragma unroll
        for (int i = 0; i < 2; i++) {
            int id = tid + 512 * i;
            int ar = id >> 3, ac = id & 7;
            int r = row0 + ar;
            int rc = r < M ? r : (M - 1);
            cp_async16((uint32_t)__cvta_generic_to_shared(&As[ar * GAPAD + ac * 4]),
                       &A[(size_t)rc * lda + ac * 4], r < M ? 16 : 0);
            int br = id >> 5, bc = id & 31;
            cp_async16((uint32_t)__cvta_generic_to_shared(&Bhs[br * GBPAD + bc * 4]),
                       &Bh_g[(size_t)br * ldb + col0 + bc * 4], 16);
            cp_async16((uint32_t)__cvta_generic_to_shared(&Bls[br * GBPAD + bc * 4]),
                       &Bl_g[(size_t)br * ldb + col0 + bc * 4], 16);
        }
        cp_commit();
    }

    for (int kt = 0; kt < ktiles; kt++) {
        if (kt + 1 < ktiles) {
            float* As  = gsm + ((kt + 1) & 1) * GSTAGE;
            float* Bhs = As + G_AS;
            float* Bls = Bhs + G_BS;
            int k0 = (kt + 1) << 5;
            #pragma unroll
            for (int i = 0; i < 2; i++) {
                int id = tid + 512 * i;
                int ar = id >> 3, ac = id & 7;
                int r = row0 + ar;
                int rc = r < M ? r : (M - 1);
                cp_async16((uint32_t)__cvta_generic_to_shared(&As[ar * GAPAD + ac * 4]),
                           &A[(size_t)rc * lda + k0 + ac * 4], r < M ? 16 : 0);
                int br = id >> 5, bc = id & 31;
                cp_async16((uint32_t)__cvta_generic_to_shared(&Bhs[br * GBPAD + bc * 4]),
                           &Bh_g[(size_t)(k0 + br) * ldb + col0 + bc * 4], 16);
                cp_async16((uint32_t)__cvta_generic_to_shared(&Bls[br * GBPAD + bc * 4]),
                           &Bl_g[(size_t)(k0 + br) * ldb + col0 + bc * 4], 16);
            }
            cp_commit();
            cp_wait<1>();
        } else {
            cp_wait<0>();
        }
        __syncthreads();

        const float* As  = gsm + (kt & 1) * GSTAGE;
        const float* Bhs = As + G_AS;
        const float* Bls = Bhs + G_BS;

        #pragma unroll
        for (int ks = 0; ks < 4; ks++) {
            const int k = ks * 8;
            uint32_t ah[2][4], al[2][4];
            #pragma unroll
            for (int mt = 0; mt < 2; mt++) {
                int r0 = wm * 32 + mt * 16 + g;
                float x0 = As[r0 * GAPAD + k + t];
                float x1 = As[(r0 + 8) * GAPAD + k + t];
                float x2 = As[r0 * GAPAD + k + t + 4];
                float x3 = As[(r0 + 8) * GAPAD + k + t + 4];
                split_tf32(x0, ah[mt][0], al[mt][0]);
                split_tf32(x1, ah[mt][1], al[mt][1]);
                split_tf32(x2, ah[mt][2], al[mt][2]);
                split_tf32(x3, ah[mt][3], al[mt][3]);
            }
            #pragma unroll
            for (int nt = 0; nt < 4; nt++) {
                int c = wn * 32 + nt * 8 + g;
                uint32_t bh0 = __float_as_uint(Bhs[(k + t) * GBPAD + c]);
                uint32_t bh1 = __float_as_uint(Bhs[(k + t + 4) * GBPAD + c]);
                uint32_t bl0 = __float_as_uint(Bls[(k + t) * GBPAD + c]);
                uint32_t bl1 = __float_as_uint(Bls[(k + t + 4) * GBPAD + c]);
                #pragma unroll
                for (int mt = 0; mt < 2; mt++) {
                    mma_tf32(d[mt][nt], ah[mt][0], ah[mt][1], ah[mt][2], ah[mt][3], bh0, bh1);
                    mma_tf32(d[mt][nt], ah[mt][0], ah[mt][1], ah[mt][2], ah[mt][3], bl0, bl1);
                    mma_tf32(d[mt][nt], al[mt][0], al[mt][1], al[mt][2], al[mt][3], bh0, bh1);
                }
            }
        }
        __syncthreads();
    }

    #pragma unroll
    for (int mt = 0; mt < 2; mt++) {
        #pragma unroll
        for (int nt = 0; nt < 4; nt++) {
            int r = row0 + wm * 32 + mt * 16 + g;
            int c = col0 + wn * 32 + nt * 8 + 2 * t;
            float2 bz = *(const float2*)&bias[c];
            if (r < M) {
                float2 o = make_float2(d[mt][nt][0] + bz.x, d[mt][nt][1] + bz.y);
                *(float2*)&C[(size_t)r * ldc + c] = o;
            }
            if (r + 8 < M) {
                float2 o = make_float2(d[mt][nt][2] + bz.x, d[mt][nt][3] + bz.y);
                *(float2*)&C[(size_t)(r + 8) * ldc + c] = o;
            }
        }
    }
}

// ---------------- sentence-level graph attention ----------------
__global__ __launch_bounds__(256) void sent_attn(
    const float* __restrict__ qs, const float* __restrict__ ksn,
    const float* __restrict__ vsn, const float* __restrict__ bias_s,
    const float* __restrict__ gab,
    float* __restrict__ attns_out, float* __restrict__ ctxs_out)
{
    const int h = blockIdx.x, b = blockIdx.y;
    const int q = threadIdx.x;

    __shared__ float Ks[NSd][DKd + 1];
    __shared__ float Vs[NSd][DKd + 1];
    __shared__ float G[NSd][NSd + 1];

    for (int idx = q; idx < NSd * DKd; idx += 256) {
        int s = idx >> 6, k = idx & 63;
        Ks[s][k] = ksn[(size_t)(b * NSd + s) * Dd + h * DKd + k];
        Vs[s][k] = vsn[(size_t)(b * NSd + s) * Dd + h * DKd + k];
    }
    for (int idx = q; idx < NSd * NSd; idx += 256) {
        int s = idx / NSd, tt = idx % NSd;
        G[s][tt] = gab[((size_t)(b * Hd + h) * NSd + s) * NSd + tt];
    }
    __syncthreads();

    float qreg[DKd];
    const float* qrow = qs + (size_t)(b * LQd + q) * Dd + h * DKd;
    #pragma unroll
    for (int k = 0; k < DKd; k++) qreg[k] = qrow[k] * 0.125f;

    float a[NSd];
    const float* bsrow = bias_s + ((size_t)(b * Hd + h) * LQd + q) * NSd;
    #pragma unroll
    for (int s = 0; s < NSd; s++) {
        float dd = 0.f;
        #pragma unroll
        for (int k = 0; k < DKd; k++) dd += qreg[k] * Ks[s][k];
        a[s] = dd + bsrow[s];
    }

    float m = -1e30f;
    #pragma unroll
    for (int s = 0; s < NSd; s++) m = fmaxf(m, a[s]);
    float smx[NSd]; float sum = 0.f;
    #pragma unroll
    for (int s = 0; s < NSd; s++) { smx[s] = __expf(a[s] - m); sum += smx[s]; }
    float inv = 1.f / sum;

    float gg[NSd];
    #pragma unroll
    for (int tt = 0; tt < NSd; tt++) {
        float dd = 0.f;
        #pragma unroll
        for (int s = 0; s < NSd; s++) dd += smx[s] * G[s][tt];
        gg[tt] = dd * inv;
    }
    #pragma unroll
    for (int s = 0; s < NSd; s++) a[s] -= 0.5f * gg[s] * gg[s];

    m = -1e30f;
    #pragma unroll
    for (int s = 0; s < NSd; s++) m = fmaxf(m, a[s]);
    sum = 0.f;
    #pragma unroll
    for (int s = 0; s < NSd; s++) { a[s] = __expf(a[s] - m); sum += a[s]; }
    inv = 1.f / sum;

    float* arow = attns_out + ((size_t)(b * Hd + h) * LQd + q) * NSd;
    #pragma unroll
    for (int s = 0; s < NSd; s++) { a[s] *= inv; arow[s] = a[s]; }

    float* crow = ctxs_out + (size_t)(b * LQd + q) * Dd + h * DKd;
    #pragma unroll
    for (int dd = 0; dd < DKd; dd++) {
        float acc = 0.f;
        #pragma unroll
        for (int s = 0; s < NSd; s++) acc += a[s] * Vs[s][dd];
        crow[dd] = acc;
    }
}

// ---------------- word-level attention (tensor-core, 3xTF32) ----------------
#define WQPAD 68
#define WKPAD 68
#define WPPAD 132
#define WSM_QH 0
#define WSM_QL (32 * WQPAD)
#define WSM_K  (2 * 32 * WQPAD)
#define WSM_V  (WSM_K + 128 * WKPAD)
#define WSM_P  (WSM_V + 128 * WKPAD)
#define WSMEM_WORDS (WSM_P + 32 * WPPAD)   // 25984 floats

__global__ __launch_bounds__(256) void word_attn_tc(
    const float* __restrict__ qw, const float* __restrict__ kw,
    const float* __restrict__ vw, const float* __restrict__ bias_w,
    const float* __restrict__ attns, float* __restrict__ ctxw)
{
    extern __shared__ float wsm[];
    uint32_t* Qh = (uint32_t*)(wsm + WSM_QH);
    uint32_t* Ql = (uint32_t*)(wsm + WSM_QL);
    float* Ks = wsm + WSM_K;
    float* Vs = wsm + WSM_V;
    float* Ps = wsm + WSM_P;

    const int tid = threadIdx.x;
    const int wid = tid >> 5;
    const int lane = tid & 31;
    const int g = lane >> 2;
    const int t = lane & 3;
    const int wm = wid & 1;
    const int wn = wid >> 1;
    const int q0 = blockIdx.x * 32;
    const int h  = blockIdx.y;
    const int b  = blockIdx.z;

    #pragma unroll
    for (int i = 0; i < 2; i++) {
        int id = tid + 256 * i;
        int qr = id >> 4, qc = id & 15;
        float4 v = *(const float4*)(qw + (size_t)(b * LQd + q0 + qr) * Dd + h * DKd + qc * 4);
        float vv[4] = {v.x * 0.125f, v.y * 0.125f, v.z * 0.125f, v.w * 0.125f};
        #pragma unroll
        for (int j = 0; j < 4; j++) {
            uint32_t hi, lo;
            split_tf32(vv[j], hi, lo);
            Qh[qr * WQPAD + qc * 4 + j] = hi;
            Ql[qr * WQPAD + qc * 4 + j] = lo;
        }
    }

    float oacc[2][4];
    #pragma unroll
    for (int nt = 0; nt < 2; nt++)
        #pragma unroll
        for (int j = 0; j < 4; j++) oacc[nt][j] = 0.f;

    for (int s = 0; s < NSd; s++) {
        __syncthreads();
        const float* kb = kw + (size_t)(b * NSd + s) * NTd * Dd + h * DKd;
        const float* vb = vw + (size_t)(b * NSd + s) * NTd * Dd + h * DKd;
        #pragma unroll
        for (int i = 0; i < 8; i++) {
            int id = tid + 256 * i;
            int kr = id >> 4, kc = id & 15;
            float4 kv = *(const float4*)(kb + (size_t)kr * Dd + kc * 4);
            *(float4*)&Ks[kr * WKPAD + kc * 4] = kv;
            float4 vv = *(const float4*)(vb + (size_t)kr * Dd + kc * 4);
            *(float4*)&Vs[kr * WKPAD + kc * 4] = vv;
        }
        __syncthreads();

        float pacc[4][4];
        #pragma unroll
        for (int nt = 0; nt < 4; nt++)
            #pragma unroll
            for (int j = 0; j < 4; j++) pacc[nt][j] = 0.f;

        #pragma unroll
        for (int ks = 0; ks < 8; ks++) {
            const int k = ks * 8;
            int r0 = wm * 16 + g;
            uint32_t ah0 = Qh[r0 * WQPAD + k + t];
            uint32_t ah1 = Qh[(r0 + 8) * WQPAD + k + t];
            uint32_t ah2 = Qh[r0 * WQPAD + k + t + 4];
            uint32_t ah3 = Qh[(r0 + 8) * WQPAD + k + t + 4];
            uint32_t al0 = Ql[r0 * WQPAD + k + t];
            uint32_t al1 = Ql[(r0 + 8) * WQPAD + k + t];
            uint32_t al2 = Ql[r0 * WQPAD + k + t + 4];
            uint32_t al3 = Ql[(r0 + 8) * WQPAD + k + t + 4];
            #pragma unroll
            for (int nt = 0; nt < 4; nt++) {
                int c = wn * 32 + nt * 8 + g;
                float y0 = Ks[c * WKPAD + k + t];
                float y1 = Ks[c * WKPAD + k + t + 4];
                uint32_t bh0, bl0, bh1, bl1;
                split_tf32(y0, bh0, bl0);
                split_tf32(y1, bh1, bl1);
                mma_tf32(pacc[nt], ah0, ah1, ah2, ah3, bh0, bh1);
                mma_tf32(pacc[nt], ah0, ah1, ah2, ah3, bl0, bl1);
                mma_tf32(pacc[nt], al0, al1, al2, al3, bh0, bh1);
            }
        }
        #pragma unroll
        for (int nt = 0; nt < 4; nt++) {
            int r = wm * 16 + g;
            int c = wn * 32 + nt * 8 + 2 * t;
            *(float2*)&Ps[r * WPPAD + c] = make_float2(pacc[nt][0], pacc[nt][1]);
            *(float2*)&Ps[(r + 8) * WPPAD + c] = make_float2(pacc[nt][2], pacc[nt][3]);
        }
        __syncthreads();

        const float* bb = bias_w + ((size_t)((b * NSd + s) * Hd + h) * LQd + q0) * NTd;
        #pragma unroll
        for (int rr = 0; rr < 4; rr++) {
            int r = wid * 4 + rr;
            float x0 = Ps[r * WPPAD + lane]       + bb[r * NTd + lane];
            float x1 = Ps[r * WPPAD + lane + 32]  + bb[r * NTd + lane + 32];
            float x2 = Ps[r * WPPAD + lane + 64]  + bb[r * NTd + lane + 64];
            float x3 = Ps[r * WPPAD + lane + 96]  + bb[r * NTd + lane + 96];
            float mx = fmaxf(fmaxf(x0, x1), fmaxf(x2, x3));
            #pragma unroll
            for (int o = 16; o; o >>= 1) mx = fmaxf(mx, __shfl_xor_sync(0xffffffffu, mx, o));
            x0 = __expf(x0 - mx); x1 = __expf(x1 - mx);
            x2 = __expf(x2 - mx); x3 = __expf(x3 - mx);
            float su = x0 + x1 + x2 + x3;
            #pragma unroll
            for (int o = 16; o; o >>= 1) su += __shfl_xor_sync(0xffffffffu, su, o);
            float wsc = attns[((size_t)(b * Hd + h) * LQd + q0 + r) * NSd + s] / su;
            Ps[r * WPPAD + lane]      = x0 * wsc;
            Ps[r * WPPAD + lane + 32] = x1 * wsc;
            Ps[r * WPPAD + lane + 64] = x2 * wsc;
            Ps[r * WPPAD + lane + 96] = x3 * wsc;
        }
        __syncthreads();

        #pragma unroll
        for (int ks = 0; ks < 16; ks++) {
            const int k = ks * 8;
            int r0 = wm * 16 + g;
            float p0 = Ps[r0 * WPPAD + k + t];
            float p1 = Ps[(r0 + 8) * WPPAD + k + t];
            float p2 = Ps[r0 * WPPAD + k + t + 4];
            float p3 = Ps[(r0 + 8) * WPPAD + k + t + 4];
            uint32_t ah0, al0, ah1, al1, ah2, al2, ah3, al3;
            split_tf32(p0, ah0, al0);
            split_tf32(p1, ah1, al1);
            split_tf32(p2, ah2, al2);
            split_tf32(p3, ah3, al3);
            #pragma unroll
            for (int nt = 0; nt < 2; nt++) {
                int c = wn * 16 + nt * 8 + g;
                float y0 = Vs[(k + t) * WKPAD + c];
                float y1 = Vs[(k + t + 4) * WKPAD + c];
                uint32_t bh0, bl0, bh1, bl1;
                split_tf32(y0, bh0, bl0);
                split_tf32(y1, bh1, bl1);
                mma_tf32(oacc[nt], ah0, ah1, ah2, ah3, bh0, bh1);
                mma_tf32(oacc[nt], ah0, ah1, ah2, ah3, bl0, bl1);
                mma_tf32(oacc[nt], al0, al1, al2, al3, bh0, bh1);
            }
        }
    }

    #pragma unroll
    for (int nt = 0; nt < 2; nt++) {
        int r = q0 + wm * 16 + g;
        int c = h * DKd + wn * 16 + nt * 8 + 2 * t;
        *(float2*)&ctxw[(size_t)(b * LQd + r) * Dd + c] =
            make_float2(oacc[nt][0], oacc[nt][1]);
        *(float2*)&ctxw[(size_t)(b * LQd + r + 8) * Dd + c] =
            make_float2(oacc[nt][2], oacc[nt][3]);
    }
}

// ---------------- host ----------------
extern "C" void kernel_launch(void* const* d_in, const int* in_sizes, int n_in,
                              void* d_out, int out_size)
{
    const float* q      = (const float*)d_in[0];
    const float* k_s    = (const float*)d_in[1];
    const float* v_s    = (const float*)d_in[2];
    const float* k_w    = (const float*)d_in[3];
    const float* v_w    = (const float*)d_in[4];
    const float* bias_w = (const float*)d_in[5];
    const float* bias_s = (const float*)d_in[6];
    const float* gab    = (const float*)d_in[7];

    const float *wq_s, *bq_s, *wk_s, *bk_s, *wv_s, *bv_s;
    const float *wq_w, *bq_w, *wk_w, *bk_w, *wv_w, *bv_w;
    const float *fcs_w, *fcs_b, *fcw_w, *fcw_b, *fco_w, *fco_b;

    if (in_sizes[9] == 512) {
        wq_s = (const float*)d_in[8];  bq_s = (const float*)d_in[9];
        wk_s = (const float*)d_in[10]; bk_s = (const float*)d_in[11];
        wv_s = (const float*)d_in[12]; bv_s = (const float*)d_in[13];
        wq_w = (const float*)d_in[14]; bq_w = (const float*)d_in[15];
        wk_w = (const float*)d_in[16]; bk_w = (const float*)d_in[17];
        wv_w = (const float*)d_in[18]; bv_w = (const float*)d_in[19];
        fcs_w = (const float*)d_in[20]; fcs_b = (const float*)d_in[21];
        fcw_w = (const float*)d_in[22]; fcw_b = (const float*)d_in[23];
        fco_w = (const float*)d_in[24]; fco_b = (const float*)d_in[25];
    } else {
        wq_s = (const float*)d_in[8];  wk_s = (const float*)d_in[9];
        wv_s = (const float*)d_in[10]; wq_w = (const float*)d_in[11];
        wk_w = (const float*)d_in[12]; wv_w = (const float*)d_in[13];
        fcs_w = (const float*)d_in[14]; fcw_w = (const float*)d_in[15];
        bq_s = (const float*)d_in[16]; bk_s = (const float*)d_in[17];
        bv_s = (const float*)d_in[18]; bq_w = (const float*)d_in[19];
        bk_w = (const float*)d_in[20]; bv_w = (const float*)d_in[21];
        fcs_b = (const float*)d_in[22]; fcw_b = (const float*)d_in[23];
        fco_w = (const float*)d_in[24]; fco_b = (const float*)d_in[25];
    }

    float* scratch = nullptr;
    cudaGetSymbolAddress((void**)&scratch, g_scratch);
    float* s_qs   = scratch + OFF_QS;
    float* s_qw   = scratch + OFF_QW;
    float* s_ks   = scratch + OFF_KS;
    float* s_vs   = scratch + OFF_VS;
    float* s_kw   = scratch + OFF_KW;
    float* s_vw   = scratch + OFF_VW;
    float* s_att  = scratch + OFF_ATT;
    float* s_ctxs = scratch + OFF_CTXS;
    float* s_ctxw = scratch + OFF_CTXW;
    float* s_cat  = scratch + OFF_CAT;
    float* wh     = scratch + OFF_WH;
    float* wl     = scratch + OFF_WL;

    cudaFuncSetAttribute(gemm_tc2, cudaFuncAttributeMaxDynamicSharedMemorySize, GSMEM_BYTES);
    cudaFuncSetAttribute(word_attn_tc, cudaFuncAttributeMaxDynamicSharedMemorySize,
                         WSMEM_WORDS * (int)sizeof(float));

    // 0) split weights once
    PrepArgs pa;
    pa.src[0] = wq_s; pa.src[1] = wk_s; pa.src[2] = wv_s;
    pa.src[3] = wq_w; pa.src[4] = wk_w; pa.src[5] = wv_w;
    pa.src[6] = fcs_w; pa.src[7] = fcw_w; pa.src[8] = fco_w;
    prep_split<<<dim3(128, 9), 256>>>(pa, wh, wl);

    #define WHp(i) (wh + WOFF(i))
    #define WLp(i) (wl + WOFF(i))

    dim3 blk(512);

    // q projections: z=0 -> q@wq_s, z=1 -> q@wq_w
    gemm_tc2<<<dim3(4, 8, 2), blk, GSMEM_BYTES>>>(
        q, q, WHp(0), WLp(0), WHp(3), WLp(3), bq_s, bq_w, s_qs, s_qw,
        1024, 512, 512, 512, 512, 512);
    // sentence k/v projections
    gemm_tc2<<<dim3(4, 1, 2), blk, GSMEM_BYTES>>>(
        k_s, v_s, WHp(1), WLp(1), WHp(2), WLp(2), bk_s, bv_s, s_ks, s_vs,
        96, 512, 512, 512, 512, 512);
    // word k/v projections (big)
    gemm_tc2<<<dim3(4, 96, 2), blk, GSMEM_BYTES>>>(
        k_w, v_w, WHp(4), WLp(4), WHp(5), WLp(5), bk_w, bv_w, s_kw, s_vw,
        12288, 512, 512, 512, 512, 512);

    sent_attn<<<dim3(Hd, BB), 256>>>(s_qs, s_ks, s_vs, bias_s, gab, s_att, s_ctxs);

    word_attn_tc<<<dim3(LQd / 32, Hd, BB), 256, WSMEM_WORDS * sizeof(float)>>>(
        s_qw, s_kw, s_vw, bias_w, s_att, s_ctxw);

    // fcs / fcw into cat
    gemm_tc2<<<dim3(4, 8, 2), blk, GSMEM_BYTES>>>(
        s_ctxs, s_ctxw, WHp(6), WLp(6), WHp(7), WLp(7), fcs_b, fcw_b,
        s_cat, s_cat + 512,
        1024, 512, 512, 512, 512, 1024);
    // final fco
    gemm_tc2<<<dim3(4, 8, 1), blk, GSMEM_BYTES>>>(
        s_cat, s_cat, WHp(8), WLp(8), WHp(8), WLp(8), fco_b, fco_b,
        (float*)d_out, (float*)d_out,
        1024, 512, 1024, 1024, 512, 512);
}